// round 1
// baseline (speedup 1.0000x reference)
#include <cuda_runtime.h>
#include <cuda_bf16.h>
#include <cstdint>

// ---------------------------------------------------------------------------
// DeepFM: out = bias + first + second + MLP(emb)
// B=16384, F=26, V=100000, D=64, ND=13, H1=1024, H2=512, H3=256
// Strategy:
//   K_embed : gather embeddings (fp32 exact) -> first/second order into out,
//             h[B,1728] as bf16
//   K_conv  : W1/W2/W3 fp32 -> bf16 scratch
//   K_gemm  : bf16 mma.sync 128x128x32 tiled GEMM + fused relu (x3)
//   K_final : out += h3 @ Wout
// ---------------------------------------------------------------------------

namespace cfg {
constexpr int B  = 16384;
constexpr int F  = 26;
constexpr int V  = 100000;
constexpr int D  = 64;
constexpr int ND = 13;
constexpr int H1 = 1024;
constexpr int H2 = 512;
constexpr int H3 = 256;
constexpr int K0 = (F + 1) * D;  // 1728
}

// ------------------------- scratch (device globals) ------------------------
__device__ __nv_bfloat16 g_h [(size_t)cfg::B * cfg::K0];
__device__ __nv_bfloat16 g_h1[(size_t)cfg::B * cfg::H1];
__device__ __nv_bfloat16 g_h2[(size_t)cfg::B * cfg::H2];
__device__ __nv_bfloat16 g_h3[(size_t)cfg::B * cfg::H3];
__device__ __nv_bfloat16 g_W1[cfg::K0 * cfg::H1];
__device__ __nv_bfloat16 g_W2[cfg::H1 * cfg::H2];
__device__ __nv_bfloat16 g_W3[cfg::H2 * cfg::H3];

// ------------------------- weight conversion -------------------------------
__global__ void convert_weights(const float* __restrict__ W1,
                                const float* __restrict__ W2,
                                const float* __restrict__ W3) {
    const int n1 = cfg::K0 * cfg::H1;
    const int n2 = cfg::H1 * cfg::H2;
    const int n3 = cfg::H2 * cfg::H3;
    const int total = n1 + n2 + n3;
    for (int i = blockIdx.x * blockDim.x + threadIdx.x; i < total;
         i += gridDim.x * blockDim.x) {
        if (i < n1)            g_W1[i]           = __float2bfloat16(W1[i]);
        else if (i < n1 + n2)  g_W2[i - n1]      = __float2bfloat16(W2[i - n1]);
        else                   g_W3[i - n1 - n2] = __float2bfloat16(W3[i - n1 - n2]);
    }
}

// ------------------------- embed + FM (fp32 exact) -------------------------
// 256 threads/block = 4 rows x 64 lanes (lane = embedding dim d)
__global__ __launch_bounds__(256) void embed_kernel(
    const float* __restrict__ dense,       // [B, ND]
    const int*   __restrict__ sidx,        // [B, F]
    const float* __restrict__ bias,        // [1,1]
    const float* __restrict__ emb_tables,  // [F, V, D]
    const float* __restrict__ lin_tables,  // [F, V]
    const float* __restrict__ Wd,          // [ND, D]
    const float* __restrict__ Wld,         // [ND, 1]
    const float* __restrict__ bld,         // [1]
    float* __restrict__ out)               // [B]
{
    const int sub = threadIdx.x >> 6;    // 0..3
    const int d   = threadIdx.x & 63;    // 0..63
    const int row = blockIdx.x * 4 + sub;

    const float* dr = dense + (size_t)row * cfg::ND;

    // dense embedding: dense_emb[d] = sum_i dense[i] * Wd[i, d]
    float de = 0.f;
#pragma unroll
    for (int i = 0; i < cfg::ND; i++) de += dr[i] * Wd[i * cfg::D + d];

    float s  = de;
    float sq = de * de;
    g_h[(size_t)row * cfg::K0 + d] = __float2bfloat16(de);

    // sparse gathers (coalesced: 64 lanes x 4B = full 256B row)
#pragma unroll 4
    for (int f = 0; f < cfg::F; f++) {
        int idx = sidx[(size_t)row * cfg::F + f];
        float e = emb_tables[((size_t)f * cfg::V + idx) * cfg::D + d];
        s  += e;
        sq += e * e;
        g_h[(size_t)row * cfg::K0 + (size_t)(f + 1) * cfg::D + d] =
            __float2bfloat16(e);
    }

    // per-lane contribution: FM second order + linear terms spread over lanes
    float val = 0.5f * (s * s - sq);
    if (d < cfg::F) {
        int idx = sidx[(size_t)row * cfg::F + d];
        val += lin_tables[(size_t)d * cfg::V + idx];
    }
    if (d < cfg::ND) val += dr[d] * Wld[d];

    // reduce across the 64-lane group (2 warps)
#pragma unroll
    for (int o = 16; o > 0; o >>= 1)
        val += __shfl_down_sync(0xffffffffu, val, o);

    __shared__ float red[8];
    if ((threadIdx.x & 31) == 0) red[threadIdx.x >> 5] = val;
    __syncthreads();
    if (d == 0)
        out[row] = bias[0] + bld[0] + red[sub * 2] + red[sub * 2 + 1];
}

// ------------------------- bf16 tensor-core GEMM ---------------------------
#define BM 128
#define BN 128
#define BK 32
#define ASTR 40    // BK + 8 pad -> conflict-free ldmatrix (stride 80B)
#define BSTR 136   // BN + 8 pad -> conflict-free ldmatrix (stride 272B)

__device__ __forceinline__ uint32_t smem_u32(const void* p) {
    return (uint32_t)__cvta_generic_to_shared(p);
}
__device__ __forceinline__ void cp16(uint32_t s, const void* g) {
    asm volatile("cp.async.cg.shared.global [%0], [%1], 16;\n" ::"r"(s), "l"(g));
}
__device__ __forceinline__ void cp_commit() {
    asm volatile("cp.async.commit_group;\n");
}
template <int N> __device__ __forceinline__ void cp_wait() {
    asm volatile("cp.async.wait_group %0;\n" ::"n"(N));
}
__device__ __forceinline__ void ldm_x4(uint32_t a, uint32_t& r0, uint32_t& r1,
                                       uint32_t& r2, uint32_t& r3) {
    asm volatile("ldmatrix.sync.aligned.m8n8.x4.shared.b16 {%0,%1,%2,%3}, [%4];\n"
                 : "=r"(r0), "=r"(r1), "=r"(r2), "=r"(r3)
                 : "r"(a));
}
__device__ __forceinline__ void ldm_x4_t(uint32_t a, uint32_t& r0, uint32_t& r1,
                                         uint32_t& r2, uint32_t& r3) {
    asm volatile("ldmatrix.sync.aligned.m8n8.x4.trans.shared.b16 {%0,%1,%2,%3}, [%4];\n"
                 : "=r"(r0), "=r"(r1), "=r"(r2), "=r"(r3)
                 : "r"(a));
}
__device__ __forceinline__ void mma16816(float* c, const uint32_t* a,
                                         uint32_t b0, uint32_t b1) {
    asm volatile(
        "mma.sync.aligned.m16n8k16.row.col.f32.bf16.bf16.f32 "
        "{%0,%1,%2,%3}, {%4,%5,%6,%7}, {%8,%9}, {%0,%1,%2,%3};\n"
        : "+f"(c[0]), "+f"(c[1]), "+f"(c[2]), "+f"(c[3])
        : "r"(a[0]), "r"(a[1]), "r"(a[2]), "r"(a[3]), "r"(b0), "r"(b1));
}

// C[M,N] = relu(A[M,K] @ W[K,N]); all bf16 in/out, fp32 accumulate.
// 256 threads, warp grid 4(M) x 2(N): warp tile 32x64.
__global__ __launch_bounds__(256, 2) void gemm_relu_bf16(
    const __nv_bfloat16* __restrict__ A, const __nv_bfloat16* __restrict__ Wt,
    __nv_bfloat16* __restrict__ C, int M, int N, int K)
{
    __shared__ __align__(16) __nv_bfloat16 sA[2][BM * ASTR];
    __shared__ __align__(16) __nv_bfloat16 sB[2][BK * BSTR];

    const int tid  = threadIdx.x;
    const int bm   = blockIdx.y * BM;
    const int bn   = blockIdx.x * BN;
    const int wid  = tid >> 5;
    const int lane = tid & 31;
    const int wm   = (wid & 3) * 32;
    const int wn   = (wid >> 2) * 64;

    auto load_tiles = [&](int buf, int kt) {
#pragma unroll
        for (int it = 0; it < 2; it++) {          // A: 512 x 16B
            int c = tid + it * 256;
            int r = c >> 2, cg = c & 3;
            cp16(smem_u32(&sA[buf][r * ASTR + cg * 8]),
                 A + (size_t)(bm + r) * K + kt + cg * 8);
        }
#pragma unroll
        for (int it = 0; it < 2; it++) {          // B: 512 x 16B
            int c = tid + it * 256;
            int r = c >> 4, cg = c & 15;
            cp16(smem_u32(&sB[buf][r * BSTR + cg * 8]),
                 Wt + (size_t)(kt + r) * N + bn + cg * 8);
        }
        cp_commit();
    };

    float acc[2][8][4];
#pragma unroll
    for (int i = 0; i < 2; i++)
#pragma unroll
        for (int j = 0; j < 8; j++)
#pragma unroll
            for (int k = 0; k < 4; k++) acc[i][j][k] = 0.f;

    const int KT = K / BK;
    load_tiles(0, 0);
    int buf = 0;
    for (int kt = 0; kt < KT; kt++) {
        if (kt + 1 < KT) {
            load_tiles(buf ^ 1, (kt + 1) * BK);
            cp_wait<1>();
        } else {
            cp_wait<0>();
        }
        __syncthreads();
#pragma unroll
        for (int ks = 0; ks < 2; ks++) {
            uint32_t af[2][4], bfm[4][4];
#pragma unroll
            for (int mi = 0; mi < 2; mi++) {
                int r   = wm + mi * 16 + (lane & 15);
                int col = ks * 16 + (lane >> 4) * 8;
                ldm_x4(smem_u32(&sA[buf][r * ASTR + col]),
                       af[mi][0], af[mi][1], af[mi][2], af[mi][3]);
            }
#pragma unroll
            for (int nj = 0; nj < 4; nj++) {
                int r   = ks * 16 + (lane & 15);
                int col = wn + nj * 16 + (lane >> 4) * 8;
                ldm_x4_t(smem_u32(&sB[buf][r * BSTR + col]),
                         bfm[nj][0], bfm[nj][1], bfm[nj][2], bfm[nj][3]);
            }
#pragma unroll
            for (int mi = 0; mi < 2; mi++)
#pragma unroll
                for (int ni = 0; ni < 8; ni++)
                    mma16816(acc[mi][ni], af[mi],
                             bfm[ni >> 1][(ni & 1) * 2],
                             bfm[ni >> 1][(ni & 1) * 2 + 1]);
        }
        __syncthreads();
        buf ^= 1;
    }

    // epilogue: relu -> bf16
    const int lr = lane >> 2, lc = (lane & 3) * 2;
#pragma unroll
    for (int mi = 0; mi < 2; mi++)
#pragma unroll
        for (int ni = 0; ni < 8; ni++) {
            int m0 = bm + wm + mi * 16 + lr;
            int n0 = bn + wn + ni * 8 + lc;
            float v0 = fmaxf(acc[mi][ni][0], 0.f);
            float v1 = fmaxf(acc[mi][ni][1], 0.f);
            float v2 = fmaxf(acc[mi][ni][2], 0.f);
            float v3 = fmaxf(acc[mi][ni][3], 0.f);
            *reinterpret_cast<__nv_bfloat162*>(C + (size_t)m0 * N + n0) =
                __floats2bfloat162_rn(v0, v1);
            *reinterpret_cast<__nv_bfloat162*>(C + (size_t)(m0 + 8) * N + n0) =
                __floats2bfloat162_rn(v2, v3);
        }
}

// ------------------------- final: out += h3 @ Wout -------------------------
__global__ __launch_bounds__(256) void final_kernel(
    const float* __restrict__ Wout, float* __restrict__ out) {
    const int gwarp = (blockIdx.x * blockDim.x + threadIdx.x) >> 5;
    const int lane  = threadIdx.x & 31;
    if (gwarp >= cfg::B) return;
    const __nv_bfloat16* hr = g_h3 + (size_t)gwarp * cfg::H3;
    float s = 0.f;
#pragma unroll
    for (int i = lane; i < cfg::H3; i += 32)
        s += __bfloat162float(hr[i]) * Wout[i];
#pragma unroll
    for (int o = 16; o > 0; o >>= 1)
        s += __shfl_down_sync(0xffffffffu, s, o);
    if (lane == 0) out[gwarp] += s;
}

// ------------------------- launch ------------------------------------------
extern "C" void kernel_launch(void* const* d_in, const int* in_sizes, int n_in,
                              void* d_out, int out_size) {
    const float* dense = (const float*)d_in[0];
    const int*   sidx  = (const int*)d_in[1];
    const float* bias  = (const float*)d_in[2];
    const float* emb   = (const float*)d_in[3];
    const float* lin   = (const float*)d_in[4];
    const float* Wd    = (const float*)d_in[5];
    const float* Wld   = (const float*)d_in[6];
    const float* bld   = (const float*)d_in[7];
    const float* W1    = (const float*)d_in[8];
    const float* W2    = (const float*)d_in[9];
    const float* W3    = (const float*)d_in[10];
    const float* Wout  = (const float*)d_in[11];
    float* out = (float*)d_out;

    void *p_h, *p_h1, *p_h2, *p_h3, *p_W1, *p_W2, *p_W3;
    cudaGetSymbolAddress(&p_h,  g_h);
    cudaGetSymbolAddress(&p_h1, g_h1);
    cudaGetSymbolAddress(&p_h2, g_h2);
    cudaGetSymbolAddress(&p_h3, g_h3);
    cudaGetSymbolAddress(&p_W1, g_W1);
    cudaGetSymbolAddress(&p_W2, g_W2);
    cudaGetSymbolAddress(&p_W3, g_W3);

    convert_weights<<<512, 256>>>(W1, W2, W3);
    embed_kernel<<<cfg::B / 4, 256>>>(dense, sidx, bias, emb, lin, Wd, Wld,
                                      bld, out);

    dim3 g1(cfg::H1 / BN, cfg::B / BM);
    gemm_relu_bf16<<<g1, 256>>>((const __nv_bfloat16*)p_h,
                                (const __nv_bfloat16*)p_W1,
                                (__nv_bfloat16*)p_h1, cfg::B, cfg::H1, cfg::K0);
    dim3 g2(cfg::H2 / BN, cfg::B / BM);
    gemm_relu_bf16<<<g2, 256>>>((const __nv_bfloat16*)p_h1,
                                (const __nv_bfloat16*)p_W2,
                                (__nv_bfloat16*)p_h2, cfg::B, cfg::H2, cfg::H1);
    dim3 g3(cfg::H3 / BN, cfg::B / BM);
    gemm_relu_bf16<<<g3, 256>>>((const __nv_bfloat16*)p_h2,
                                (const __nv_bfloat16*)p_W3,
                                (__nv_bfloat16*)p_h3, cfg::B, cfg::H3, cfg::H2);

    final_kernel<<<cfg::B * 32 / 256, 256>>>(Wout, out);
}

// round 3
// speedup vs baseline: 1.0521x; 1.0521x over previous
#include <cuda_runtime.h>
#include <cuda_bf16.h>
#include <cstdint>

// ---------------------------------------------------------------------------
// DeepFM: out = bias + first + second + MLP(emb)
// B=16384, F=26, V=100000, D=64, ND=13, H1=1024, H2=512, H3=256
//   K_embed : gather (26-deep MLP batched loads) + FM terms -> out, h bf16
//   K_conv  : W1/W2/W3 fp32 -> bf16
//   K_gemm  : bf16 mma.sync 128x128x32, 4-stage cp.async, 1 sync/iter, relu
//   K_final : out += h3 @ Wout
// NOTE: tcgen05 unavailable (harness PTX targets compute_103, not 103a).
// ---------------------------------------------------------------------------

namespace cfg {
constexpr int B  = 16384;
constexpr int F  = 26;
constexpr int V  = 100000;
constexpr int D  = 64;
constexpr int ND = 13;
constexpr int H1 = 1024;
constexpr int H2 = 512;
constexpr int H3 = 256;
constexpr int K0 = (F + 1) * D;  // 1728
}

// ------------------------- scratch (device globals) ------------------------
__device__ __nv_bfloat16 g_h [(size_t)cfg::B * cfg::K0];
__device__ __nv_bfloat16 g_h1[(size_t)cfg::B * cfg::H1];
__device__ __nv_bfloat16 g_h2[(size_t)cfg::B * cfg::H2];
__device__ __nv_bfloat16 g_h3[(size_t)cfg::B * cfg::H3];
__device__ __nv_bfloat16 g_W1[cfg::K0 * cfg::H1];
__device__ __nv_bfloat16 g_W2[cfg::H1 * cfg::H2];
__device__ __nv_bfloat16 g_W3[cfg::H2 * cfg::H3];

// ------------------------- weight conversion -------------------------------
__global__ void convert_weights(const float* __restrict__ W1,
                                const float* __restrict__ W2,
                                const float* __restrict__ W3) {
    const int n1 = cfg::K0 * cfg::H1;
    const int n2 = cfg::H1 * cfg::H2;
    const int n3 = cfg::H2 * cfg::H3;
    const int total = n1 + n2 + n3;
    for (int i = blockIdx.x * blockDim.x + threadIdx.x; i < total;
         i += gridDim.x * blockDim.x) {
        if (i < n1)            g_W1[i]           = __float2bfloat16(W1[i]);
        else if (i < n1 + n2)  g_W2[i - n1]      = __float2bfloat16(W2[i - n1]);
        else                   g_W3[i - n1 - n2] = __float2bfloat16(W3[i - n1 - n2]);
    }
}

// ------------------------- embed + FM (fp32 exact) -------------------------
// 256 threads/block = 4 rows x 64 lanes (lane = embedding dim d).
// All 26 gathers issued before first use -> MLP=26 per thread.
__global__ __launch_bounds__(256) void embed_kernel(
    const float* __restrict__ dense,       // [B, ND]
    const int*   __restrict__ sidx,        // [B, F]
    const float* __restrict__ bias,        // [1,1]
    const float* __restrict__ emb_tables,  // [F, V, D]
    const float* __restrict__ lin_tables,  // [F, V]
    const float* __restrict__ Wd,          // [ND, D]
    const float* __restrict__ Wld,         // [ND, 1]
    const float* __restrict__ bld,         // [1]
    float* __restrict__ out)               // [B]
{
    const int sub = threadIdx.x >> 6;    // 0..3
    const int d   = threadIdx.x & 63;    // 0..63
    const int row = blockIdx.x * 4 + sub;

    const float* dr = dense + (size_t)row * cfg::ND;

    // indices first (broadcast loads within the 64-lane group)
    int idx[cfg::F];
#pragma unroll
    for (int f = 0; f < cfg::F; f++) idx[f] = __ldg(sidx + (size_t)row * cfg::F + f);

    // issue ALL embedding gathers before consuming (max memory-level parallelism)
    float ev[cfg::F];
#pragma unroll
    for (int f = 0; f < cfg::F; f++)
        ev[f] = __ldg(emb_tables + ((size_t)f * cfg::V + idx[f]) * cfg::D + d);

    // linear-term gather overlapped too
    float lin = 0.f;
    if (d < cfg::F) lin = __ldg(lin_tables + (size_t)d * cfg::V + idx[d]);

    // dense embedding: dense_emb[d] = sum_i dense[i] * Wd[i, d]
    float de = 0.f;
#pragma unroll
    for (int i = 0; i < cfg::ND; i++) de += dr[i] * Wd[i * cfg::D + d];

    float s  = de;
    float sq = de * de;
    __nv_bfloat16* hrow = g_h + (size_t)row * cfg::K0;
    hrow[d] = __float2bfloat16(de);

#pragma unroll
    for (int f = 0; f < cfg::F; f++) {
        float e = ev[f];
        s  += e;
        sq += e * e;
        hrow[(size_t)(f + 1) * cfg::D + d] = __float2bfloat16(e);
    }

    float val = 0.5f * (s * s - sq) + lin;
    if (d < cfg::ND) val += dr[d] * Wld[d];

#pragma unroll
    for (int o = 16; o > 0; o >>= 1)
        val += __shfl_down_sync(0xffffffffu, val, o);

    __shared__ float red[8];
    if ((threadIdx.x & 31) == 0) red[threadIdx.x >> 5] = val;
    __syncthreads();
    if (d == 0)
        out[row] = bias[0] + bld[0] + red[sub * 2] + red[sub * 2 + 1];
}

// ------------------------- bf16 tensor-core GEMM ---------------------------
#define BM 128
#define BN 128
#define BK 32
#define NS 4       // cp.async pipeline stages
#define ASTR 40    // BK + 8 pad -> conflict-free ldmatrix
#define BSTR 136   // BN + 8 pad -> conflict-free ldmatrix
#define A_ST (BM * ASTR)          // 5120 elems / stage
#define B_ST (BK * BSTR)          // 4352 elems / stage
#define STAGE_ELEMS (A_ST + B_ST)
#define GEMM_SMEM (NS * STAGE_ELEMS * 2)   // bytes (75776)

__device__ __forceinline__ uint32_t smem_u32(const void* p) {
    return (uint32_t)__cvta_generic_to_shared(p);
}
__device__ __forceinline__ void cp16(uint32_t s, const void* g) {
    asm volatile("cp.async.cg.shared.global [%0], [%1], 16;\n" ::"r"(s), "l"(g));
}
__device__ __forceinline__ void cp_commit() {
    asm volatile("cp.async.commit_group;\n");
}
template <int N> __device__ __forceinline__ void cp_wait() {
    asm volatile("cp.async.wait_group %0;\n" ::"n"(N));
}
__device__ __forceinline__ void ldm_x4(uint32_t a, uint32_t& r0, uint32_t& r1,
                                       uint32_t& r2, uint32_t& r3) {
    asm volatile("ldmatrix.sync.aligned.m8n8.x4.shared.b16 {%0,%1,%2,%3}, [%4];\n"
                 : "=r"(r0), "=r"(r1), "=r"(r2), "=r"(r3)
                 : "r"(a));
}
__device__ __forceinline__ void ldm_x4_t(uint32_t a, uint32_t& r0, uint32_t& r1,
                                         uint32_t& r2, uint32_t& r3) {
    asm volatile("ldmatrix.sync.aligned.m8n8.x4.trans.shared.b16 {%0,%1,%2,%3}, [%4];\n"
                 : "=r"(r0), "=r"(r1), "=r"(r2), "=r"(r3)
                 : "r"(a));
}
__device__ __forceinline__ void mma16816(float* c, const uint32_t* a,
                                         uint32_t b0, uint32_t b1) {
    asm volatile(
        "mma.sync.aligned.m16n8k16.row.col.f32.bf16.bf16.f32 "
        "{%0,%1,%2,%3}, {%4,%5,%6,%7}, {%8,%9}, {%0,%1,%2,%3};\n"
        : "+f"(c[0]), "+f"(c[1]), "+f"(c[2]), "+f"(c[3])
        : "r"(a[0]), "r"(a[1]), "r"(a[2]), "r"(a[3]), "r"(b0), "r"(b1));
}

// C[M,N] = relu(A[M,K] @ W[K,N]); bf16 in/out, fp32 accum.
// 256 threads, warp grid 4(M) x 2(N): warp tile 32x64. 4-stage pipeline.
__global__ __launch_bounds__(256, 2) void gemm_relu_bf16(
    const __nv_bfloat16* __restrict__ A, const __nv_bfloat16* __restrict__ Wt,
    __nv_bfloat16* __restrict__ C, int M, int N, int K)
{
    extern __shared__ __align__(16) __nv_bfloat16 smem[];

    const int tid  = threadIdx.x;
    const int bm   = blockIdx.y * BM;
    const int bn   = blockIdx.x * BN;
    const int wid  = tid >> 5;
    const int lane = tid & 31;
    const int wm   = (wid & 3) * 32;
    const int wn   = (wid >> 2) * 64;

    auto load_tiles = [&](int buf, int kt) {
        __nv_bfloat16* sA = smem + buf * STAGE_ELEMS;
        __nv_bfloat16* sB = sA + A_ST;
#pragma unroll
        for (int it = 0; it < 2; it++) {          // A: 512 x 16B
            int c = tid + it * 256;
            int r = c >> 2, cg = c & 3;
            cp16(smem_u32(&sA[r * ASTR + cg * 8]),
                 A + (size_t)(bm + r) * K + kt + cg * 8);
        }
#pragma unroll
        for (int it = 0; it < 2; it++) {          // B: 512 x 16B
            int c = tid + it * 256;
            int r = c >> 4, cg = c & 15;
            cp16(smem_u32(&sB[r * BSTR + cg * 8]),
                 Wt + (size_t)(kt + r) * N + bn + cg * 8);
        }
    };

    float acc[2][8][4];
#pragma unroll
    for (int i = 0; i < 2; i++)
#pragma unroll
        for (int j = 0; j < 8; j++)
#pragma unroll
            for (int k = 0; k < 4; k++) acc[i][j][k] = 0.f;

    const int KT = K / BK;

    // prologue: stages 0..NS-2 (one commit group each)
#pragma unroll
    for (int s = 0; s < NS - 1; s++) {
        load_tiles(s, s * BK);
        cp_commit();
    }

    for (int kt = 0; kt < KT; kt++) {
        const int buf = kt % NS;
        cp_wait<NS - 2>();        // stage kt resident (commit-count invariant)
        __syncthreads();          // also guards overwrite of stage (kt-1)%NS

        const int pf = kt + NS - 1;
        if (pf < KT) load_tiles(pf % NS, pf * BK);
        cp_commit();              // ALWAYS commit (empty at tail) to keep count

        __nv_bfloat16* sA = smem + buf * STAGE_ELEMS;
        __nv_bfloat16* sB = sA + A_ST;
#pragma unroll
        for (int ks = 0; ks < 2; ks++) {
            uint32_t af[2][4], bfm[4][4];
#pragma unroll
            for (int mi = 0; mi < 2; mi++) {
                int r   = wm + mi * 16 + (lane & 15);
                int col = ks * 16 + (lane >> 4) * 8;
                ldm_x4(smem_u32(&sA[r * ASTR + col]),
                       af[mi][0], af[mi][1], af[mi][2], af[mi][3]);
            }
#pragma unroll
            for (int nj = 0; nj < 4; nj++) {
                int r   = ks * 16 + (lane & 15);
                int col = wn + nj * 16 + (lane >> 4) * 8;
                ldm_x4_t(smem_u32(&sB[r * BSTR + col]),
                         bfm[nj][0], bfm[nj][1], bfm[nj][2], bfm[nj][3]);
            }
#pragma unroll
            for (int mi = 0; mi < 2; mi++)
#pragma unroll
                for (int ni = 0; ni < 8; ni++)
                    mma16816(acc[mi][ni], af[mi],
                             bfm[ni >> 1][(ni & 1) * 2],
                             bfm[ni >> 1][(ni & 1) * 2 + 1]);
        }
    }

    // epilogue: relu -> bf16
    const int lr = lane >> 2, lc = (lane & 3) * 2;
#pragma unroll
    for (int mi = 0; mi < 2; mi++)
#pragma unroll
        for (int ni = 0; ni < 8; ni++) {
            int m0 = bm + wm + mi * 16 + lr;
            int n0 = bn + wn + ni * 8 + lc;
            float v0 = fmaxf(acc[mi][ni][0], 0.f);
            float v1 = fmaxf(acc[mi][ni][1], 0.f);
            float v2 = fmaxf(acc[mi][ni][2], 0.f);
            float v3 = fmaxf(acc[mi][ni][3], 0.f);
            *reinterpret_cast<__nv_bfloat162*>(C + (size_t)m0 * N + n0) =
                __floats2bfloat162_rn(v0, v1);
            *reinterpret_cast<__nv_bfloat162*>(C + (size_t)(m0 + 8) * N + n0) =
                __floats2bfloat162_rn(v2, v3);
        }
}

// ------------------------- final: out += h3 @ Wout -------------------------
__global__ __launch_bounds__(256) void final_kernel(
    const float* __restrict__ Wout, float* __restrict__ out) {
    const int gwarp = (blockIdx.x * blockDim.x + threadIdx.x) >> 5;
    const int lane  = threadIdx.x & 31;
    if (gwarp >= cfg::B) return;
    const __nv_bfloat16* hr = g_h3 + (size_t)gwarp * cfg::H3;
    float s = 0.f;
#pragma unroll
    for (int i = lane; i < cfg::H3; i += 32)
        s += __bfloat162float(hr[i]) * Wout[i];
#pragma unroll
    for (int o = 16; o > 0; o >>= 1)
        s += __shfl_down_sync(0xffffffffu, s, o);
    if (lane == 0) out[gwarp] += s;
}

// ------------------------- launch ------------------------------------------
extern "C" void kernel_launch(void* const* d_in, const int* in_sizes, int n_in,
                              void* d_out, int out_size) {
    const float* dense = (const float*)d_in[0];
    const int*   sidx  = (const int*)d_in[1];
    const float* bias  = (const float*)d_in[2];
    const float* emb   = (const float*)d_in[3];
    const float* lin   = (const float*)d_in[4];
    const float* Wd    = (const float*)d_in[5];
    const float* Wld   = (const float*)d_in[6];
    const float* bld   = (const float*)d_in[7];
    const float* W1    = (const float*)d_in[8];
    const float* W2    = (const float*)d_in[9];
    const float* W3    = (const float*)d_in[10];
    const float* Wout  = (const float*)d_in[11];
    float* out = (float*)d_out;

    void *p_h, *p_h1, *p_h2, *p_h3, *p_W1, *p_W2, *p_W3;
    cudaGetSymbolAddress(&p_h,  g_h);
    cudaGetSymbolAddress(&p_h1, g_h1);
    cudaGetSymbolAddress(&p_h2, g_h2);
    cudaGetSymbolAddress(&p_h3, g_h3);
    cudaGetSymbolAddress(&p_W1, g_W1);
    cudaGetSymbolAddress(&p_W2, g_W2);
    cudaGetSymbolAddress(&p_W3, g_W3);

    static bool attr_done = false;
    if (!attr_done) {
        cudaFuncSetAttribute(gemm_relu_bf16,
                             cudaFuncAttributeMaxDynamicSharedMemorySize,
                             GEMM_SMEM);
        attr_done = true;
    }

    convert_weights<<<512, 256>>>(W1, W2, W3);
    embed_kernel<<<cfg::B / 4, 256>>>(dense, sidx, bias, emb, lin, Wd, Wld,
                                      bld, out);

    dim3 g1(cfg::H1 / BN, cfg::B / BM);
    gemm_relu_bf16<<<g1, 256, GEMM_SMEM>>>((const __nv_bfloat16*)p_h,
                                           (const __nv_bfloat16*)p_W1,
                                           (__nv_bfloat16*)p_h1,
                                           cfg::B, cfg::H1, cfg::K0);
    dim3 g2(cfg::H2 / BN, cfg::B / BM);
    gemm_relu_bf16<<<g2, 256, GEMM_SMEM>>>((const __nv_bfloat16*)p_h1,
                                           (const __nv_bfloat16*)p_W2,
                                           (__nv_bfloat16*)p_h2,
                                           cfg::B, cfg::H2, cfg::H1);
    dim3 g3(cfg::H3 / BN, cfg::B / BM);
    gemm_relu_bf16<<<g3, 256, GEMM_SMEM>>>((const __nv_bfloat16*)p_h2,
                                           (const __nv_bfloat16*)p_W3,
                                           (__nv_bfloat16*)p_h3,
                                           cfg::B, cfg::H3, cfg::H2);

    final_kernel<<<cfg::B * 32 / 256, 256>>>(Wout, out);
}

// round 4
// speedup vs baseline: 1.0965x; 1.0422x over previous
#include <cuda_runtime.h>
#include <cuda_bf16.h>
#include <cuda_fp8.h>
#include <cstdint>

// ---------------------------------------------------------------------------
// DeepFM: out = bias + first + second + MLP(emb)
// GEMMs moved to FP8 e4m3 mma.sync (m16n8k32) — 2x legacy bf16 HMMA rate.
// Scaling: activations & weights stored as fp8 of (value*64); GEMM result
// acc = 4096*true; epilogue stores fp8(acc/64) = fp8(64*true).
// first/second-order FM terms remain exact fp32 (dominate the output).
// ---------------------------------------------------------------------------

namespace cfg {
constexpr int B  = 16384;
constexpr int F  = 26;
constexpr int V  = 100000;
constexpr int D  = 64;
constexpr int ND = 13;
constexpr int H1 = 1024;
constexpr int H2 = 512;
constexpr int H3 = 256;
constexpr int K0 = (F + 1) * D;  // 1728
}

constexpr float SCALE = 64.f;
constexpr float INV_SCALE = 1.f / 64.f;

// ------------------------- scratch (device globals) ------------------------
__device__ uint8_t g_h  [(size_t)cfg::B * cfg::K0];   // fp8 e4m3, x64
__device__ uint8_t g_h1 [(size_t)cfg::B * cfg::H1];
__device__ uint8_t g_h2 [(size_t)cfg::B * cfg::H2];
__device__ uint8_t g_h3 [(size_t)cfg::B * cfg::H3];
__device__ uint8_t g_Wt1[cfg::H1 * cfg::K0];          // [N,K] fp8, x64
__device__ uint8_t g_Wt2[cfg::H2 * cfg::H1];
__device__ uint8_t g_Wt3[cfg::H3 * cfg::H2];

__device__ __forceinline__ uint8_t to_fp8(float v) {
    return (uint8_t)__nv_cvt_float_to_fp8(v, __NV_SATFINITE, __NV_E4M3);
}
__device__ __forceinline__ float from_fp8(uint8_t v) {
    return __half2float(__nv_cvt_fp8_to_halfraw(v, __NV_E4M3));
}

// ------------------------- weight transpose+convert ------------------------
// out[n*K + k] = fp8(in[k*N + n] * 64)
__global__ __launch_bounds__(256) void transpose_convert(
    const float* __restrict__ in, uint8_t* __restrict__ out, int K, int N) {
    __shared__ float t[32][33];
    const int tx = threadIdx.x & 31, ty = threadIdx.x >> 5;  // 32x8
    const int n0 = blockIdx.x * 32, k0 = blockIdx.y * 32;
#pragma unroll
    for (int j = 0; j < 4; j++)
        t[ty + j * 8][tx] = in[(size_t)(k0 + ty + j * 8) * N + n0 + tx];
    __syncthreads();
#pragma unroll
    for (int j = 0; j < 4; j++)
        out[(size_t)(n0 + ty + j * 8) * K + k0 + tx] =
            to_fp8(t[tx][ty + j * 8] * SCALE);
}

// ------------------------- embed + FM (fp32 exact) -------------------------
__global__ __launch_bounds__(256) void embed_kernel(
    const float* __restrict__ dense, const int* __restrict__ sidx,
    const float* __restrict__ bias, const float* __restrict__ emb_tables,
    const float* __restrict__ lin_tables, const float* __restrict__ Wd,
    const float* __restrict__ Wld, const float* __restrict__ bld,
    float* __restrict__ out) {
    const int sub = threadIdx.x >> 6;
    const int d   = threadIdx.x & 63;
    const int row = blockIdx.x * 4 + sub;

    const float* dr = dense + (size_t)row * cfg::ND;

    int idx[cfg::F];
#pragma unroll
    for (int f = 0; f < cfg::F; f++) idx[f] = __ldg(sidx + (size_t)row * cfg::F + f);

    float ev[cfg::F];
#pragma unroll
    for (int f = 0; f < cfg::F; f++)
        ev[f] = __ldg(emb_tables + ((size_t)f * cfg::V + idx[f]) * cfg::D + d);

    float lin = 0.f;
    if (d < cfg::F) lin = __ldg(lin_tables + (size_t)d * cfg::V + idx[d]);

    float de = 0.f;
#pragma unroll
    for (int i = 0; i < cfg::ND; i++) de += dr[i] * Wd[i * cfg::D + d];

    float s  = de;
    float sq = de * de;
    uint8_t* hrow = g_h + (size_t)row * cfg::K0;
    hrow[d] = to_fp8(de * SCALE);

#pragma unroll
    for (int f = 0; f < cfg::F; f++) {
        float e = ev[f];
        s  += e;
        sq += e * e;
        hrow[(size_t)(f + 1) * cfg::D + d] = to_fp8(e * SCALE);
    }

    float val = 0.5f * (s * s - sq) + lin;
    if (d < cfg::ND) val += dr[d] * Wld[d];

#pragma unroll
    for (int o = 16; o > 0; o >>= 1)
        val += __shfl_down_sync(0xffffffffu, val, o);

    __shared__ float red[8];
    if ((threadIdx.x & 31) == 0) red[threadIdx.x >> 5] = val;
    __syncthreads();
    if (d == 0)
        out[row] = bias[0] + bld[0] + red[sub * 2] + red[sub * 2 + 1];
}

// ------------------------- FP8 tensor-core GEMM ----------------------------
// C = relu(A @ W) in scaled-fp8.  A: [M,K] fp8 row-major, Wt: [N,K] fp8.
// Tile 128x128, BK=64 fp8 per iter (2 x k32 mma steps), 4-stage cp.async.
#define BM 128
#define BN 128
#define BK 64
#define NS 4
#define TSTR 80                     // 64B row + 16B pad (5x16B: conflict-free)
#define A_ST (BM * TSTR)            // bytes per A stage (10240)
#define B_ST (BN * TSTR)            // bytes per B stage (10240)
#define STAGE_B (A_ST + B_ST)
#define GEMM_SMEM (NS * STAGE_B)    // 81920 B

__device__ __forceinline__ uint32_t smem_u32(const void* p) {
    return (uint32_t)__cvta_generic_to_shared(p);
}
__device__ __forceinline__ void cp16(uint32_t s, const void* g) {
    asm volatile("cp.async.cg.shared.global [%0], [%1], 16;\n" ::"r"(s), "l"(g));
}
__device__ __forceinline__ void cp_commit() {
    asm volatile("cp.async.commit_group;\n");
}
template <int N> __device__ __forceinline__ void cp_wait() {
    asm volatile("cp.async.wait_group %0;\n" ::"n"(N));
}
__device__ __forceinline__ void ldm_x4(uint32_t a, uint32_t& r0, uint32_t& r1,
                                       uint32_t& r2, uint32_t& r3) {
    asm volatile("ldmatrix.sync.aligned.m8n8.x4.shared.b16 {%0,%1,%2,%3}, [%4];\n"
                 : "=r"(r0), "=r"(r1), "=r"(r2), "=r"(r3)
                 : "r"(a));
}
__device__ __forceinline__ void mma_fp8(float* c, const uint32_t* a,
                                        uint32_t b0, uint32_t b1) {
    asm volatile(
        "mma.sync.aligned.m16n8k32.row.col.f32.e4m3.e4m3.f32 "
        "{%0,%1,%2,%3}, {%4,%5,%6,%7}, {%8,%9}, {%0,%1,%2,%3};\n"
        : "+f"(c[0]), "+f"(c[1]), "+f"(c[2]), "+f"(c[3])
        : "r"(a[0]), "r"(a[1]), "r"(a[2]), "r"(a[3]), "r"(b0), "r"(b1));
}

// 256 threads, warp grid 4(M) x 2(N), warp tile 32x64.
__global__ __launch_bounds__(256, 2) void gemm_relu_fp8(
    const uint8_t* __restrict__ A, const uint8_t* __restrict__ Wt,
    uint8_t* __restrict__ C, int M, int N, int K)
{
    extern __shared__ __align__(16) uint8_t smem[];

    const int tid  = threadIdx.x;
    const int bm   = blockIdx.y * BM;
    const int bn   = blockIdx.x * BN;
    const int wid  = tid >> 5;
    const int lane = tid & 31;
    const int wm   = (wid & 3) * 32;
    const int wn   = (wid >> 2) * 64;

    auto load_tiles = [&](int buf, int kofs) {
        uint8_t* sA = smem + buf * STAGE_B;
        uint8_t* sB = sA + A_ST;
        // A: 128 rows x 4 chunks of 16B  (512 chunks)
#pragma unroll
        for (int it = 0; it < 2; it++) {
            int c = tid + it * 256;
            int r = c >> 2, cg = c & 3;
            cp16(smem_u32(sA + r * TSTR + cg * 16),
                 A + (size_t)(bm + r) * K + kofs + cg * 16);
        }
        // B: 128 n-rows x 4 chunks of 16B (512 chunks)
#pragma unroll
        for (int it = 0; it < 2; it++) {
            int c = tid + it * 256;
            int r = c >> 2, cg = c & 3;
            cp16(smem_u32(sB + r * TSTR + cg * 16),
                 Wt + (size_t)(bn + r) * K + kofs + cg * 16);
        }
    };

    float acc[2][8][4];
#pragma unroll
    for (int i = 0; i < 2; i++)
#pragma unroll
        for (int j = 0; j < 8; j++)
#pragma unroll
            for (int k = 0; k < 4; k++) acc[i][j][k] = 0.f;

    const int KT = K / BK;

#pragma unroll
    for (int s = 0; s < NS - 1; s++) {
        load_tiles(s, s * BK);
        cp_commit();
    }

    for (int kt = 0; kt < KT; kt++) {
        const int buf = kt % NS;
        cp_wait<NS - 2>();
        __syncthreads();

        const int pf = kt + NS - 1;
        if (pf < KT) load_tiles(pf % NS, pf * BK);
        cp_commit();

        uint8_t* sA = smem + buf * STAGE_B;
        uint8_t* sB = sA + A_ST;
#pragma unroll
        for (int ks = 0; ks < 2; ks++) {         // two k32 steps
            // A fragments: 16x32 fp8 per mi via b16-view ldmatrix x4
            uint32_t af[2][4];
#pragma unroll
            for (int mi = 0; mi < 2; mi++) {
                int r = wm + mi * 16 + (lane & 15);
                int cb = ks * 32 + (lane >> 4) * 16;
                ldm_x4(smem_u32(sA + r * TSTR + cb),
                       af[mi][0], af[mi][1], af[mi][2], af[mi][3]);
            }
            // B fragments: n16 x k32 per nj via b16-view ldmatrix x4
            uint32_t bf[4][4];
#pragma unroll
            for (int nj = 0; nj < 4; nj++) {
                int r = wn + nj * 16 + (lane & 15);
                int cb = ks * 32 + (lane >> 4) * 16;
                ldm_x4(smem_u32(sB + r * TSTR + cb),
                       bf[nj][0], bf[nj][1], bf[nj][2], bf[nj][3]);
            }
            // r0: n(0-7) k(0-15), r1: n(8-15) k(0-15), r2: n(0-7) k(16-31),
            // r3: n(8-15) k(16-31)
#pragma unroll
            for (int mi = 0; mi < 2; mi++)
#pragma unroll
                for (int nj = 0; nj < 4; nj++) {
                    mma_fp8(acc[mi][nj * 2],     af[mi], bf[nj][0], bf[nj][2]);
                    mma_fp8(acc[mi][nj * 2 + 1], af[mi], bf[nj][1], bf[nj][3]);
                }
        }
    }

    // epilogue: relu, rescale (acc = 4096*true -> store 64*true), fp8 pairs
    const int lr = lane >> 2, lc = (lane & 3) * 2;
#pragma unroll
    for (int mi = 0; mi < 2; mi++)
#pragma unroll
        for (int ni = 0; ni < 8; ni++) {
            int m0 = bm + wm + mi * 16 + lr;
            int n0 = bn + wn + ni * 8 + lc;
            float v0 = fmaxf(acc[mi][ni][0], 0.f) * INV_SCALE;
            float v1 = fmaxf(acc[mi][ni][1], 0.f) * INV_SCALE;
            float v2 = fmaxf(acc[mi][ni][2], 0.f) * INV_SCALE;
            float v3 = fmaxf(acc[mi][ni][3], 0.f) * INV_SCALE;
            *reinterpret_cast<unsigned short*>(C + (size_t)m0 * N + n0) =
                (unsigned short)__nv_cvt_float2_to_fp8x2(
                    make_float2(v0, v1), __NV_SATFINITE, __NV_E4M3);
            *reinterpret_cast<unsigned short*>(C + (size_t)(m0 + 8) * N + n0) =
                (unsigned short)__nv_cvt_float2_to_fp8x2(
                    make_float2(v2, v3), __NV_SATFINITE, __NV_E4M3);
        }
}

// ------------------------- final: out += h3 @ Wout -------------------------
__global__ __launch_bounds__(256) void final_kernel(
    const float* __restrict__ Wout, float* __restrict__ out) {
    const int gwarp = (blockIdx.x * blockDim.x + threadIdx.x) >> 5;
    const int lane  = threadIdx.x & 31;
    if (gwarp >= cfg::B) return;
    const uint8_t* hr = g_h3 + (size_t)gwarp * cfg::H3;
    float s = 0.f;
#pragma unroll
    for (int i = lane; i < cfg::H3; i += 32)
        s += from_fp8(hr[i]) * Wout[i];
#pragma unroll
    for (int o = 16; o > 0; o >>= 1)
        s += __shfl_down_sync(0xffffffffu, s, o);
    if (lane == 0) out[gwarp] += s * INV_SCALE;   // h3 stored as 64*true
}

// ------------------------- launch ------------------------------------------
extern "C" void kernel_launch(void* const* d_in, const int* in_sizes, int n_in,
                              void* d_out, int out_size) {
    const float* dense = (const float*)d_in[0];
    const int*   sidx  = (const int*)d_in[1];
    const float* bias  = (const float*)d_in[2];
    const float* emb   = (const float*)d_in[3];
    const float* lin   = (const float*)d_in[4];
    const float* Wd    = (const float*)d_in[5];
    const float* Wld   = (const float*)d_in[6];
    const float* bld   = (const float*)d_in[7];
    const float* W1    = (const float*)d_in[8];
    const float* W2    = (const float*)d_in[9];
    const float* W3    = (const float*)d_in[10];
    const float* Wout  = (const float*)d_in[11];
    float* out = (float*)d_out;

    void *p_h, *p_h1, *p_h2, *p_h3, *p_W1, *p_W2, *p_W3;
    cudaGetSymbolAddress(&p_h,  g_h);
    cudaGetSymbolAddress(&p_h1, g_h1);
    cudaGetSymbolAddress(&p_h2, g_h2);
    cudaGetSymbolAddress(&p_h3, g_h3);
    cudaGetSymbolAddress(&p_W1, g_Wt1);
    cudaGetSymbolAddress(&p_W2, g_Wt2);
    cudaGetSymbolAddress(&p_W3, g_Wt3);

    static bool attr_done = false;
    if (!attr_done) {
        cudaFuncSetAttribute(gemm_relu_fp8,
                             cudaFuncAttributeMaxDynamicSharedMemorySize,
                             GEMM_SMEM);
        attr_done = true;
    }

    transpose_convert<<<dim3(cfg::H1 / 32, cfg::K0 / 32), 256>>>(
        W1, (uint8_t*)p_W1, cfg::K0, cfg::H1);
    transpose_convert<<<dim3(cfg::H2 / 32, cfg::H1 / 32), 256>>>(
        W2, (uint8_t*)p_W2, cfg::H1, cfg::H2);
    transpose_convert<<<dim3(cfg::H3 / 32, cfg::H2 / 32), 256>>>(
        W3, (uint8_t*)p_W3, cfg::H2, cfg::H3);

    embed_kernel<<<cfg::B / 4, 256>>>(dense, sidx, bias, emb, lin, Wd, Wld,
                                      bld, out);

    dim3 g1(cfg::H1 / BN, cfg::B / BM);
    gemm_relu_fp8<<<g1, 256, GEMM_SMEM>>>((const uint8_t*)p_h,
                                          (const uint8_t*)p_W1,
                                          (uint8_t*)p_h1,
                                          cfg::B, cfg::H1, cfg::K0);
    dim3 g2(cfg::H2 / BN, cfg::B / BM);
    gemm_relu_fp8<<<g2, 256, GEMM_SMEM>>>((const uint8_t*)p_h1,
                                          (const uint8_t*)p_W2,
                                          (uint8_t*)p_h2,
                                          cfg::B, cfg::H2, cfg::H1);
    dim3 g3(cfg::H3 / BN, cfg::B / BM);
    gemm_relu_fp8<<<g3, 256, GEMM_SMEM>>>((const uint8_t*)p_h2,
                                          (const uint8_t*)p_W3,
                                          (uint8_t*)p_h3,
                                          cfg::B, cfg::H3, cfg::H2);

    final_kernel<<<cfg::B * 32 / 256, 256>>>(Wout, out);
}